// round 17
// baseline (speedup 1.0000x reference)
#include <cuda_runtime.h>
#include <cuda_fp16.h>
#include <cstdint>

typedef uint32_t u32;

#define BATCHN 131072
#define WARPS  18
#define TPB    (WARPS * 32)
#define NCHUNK (BATCHN / 32)      // 4096 chunks of 32 rows
#define NBLOCKS 152

#define SSCALE 256.0f
#define INVS   (1.0f / 256.0f)

// smem byte layout
#define OFF_W    0                // 8 weight tiles (fp16, nt-paired), 8KB each
#define W_TILE   8192
#define OFF_A    65536            // 18 warps x 2 buffers x 4KB
#define OFF_BIAS 212992           // 6 x 64 fp32 (pre-scaled x256)
#define OFF_TV   214528           // 64 fp32
#define SMEM_BYTES 214784

extern __shared__ char smc[];

__device__ unsigned int g_ctr;

__global__ void reset_ctr() { g_ctr = 0; }

static __device__ __forceinline__ void mma_f16(float* c, const u32* a, u32 b0, u32 b1) {
    asm volatile("mma.sync.aligned.m16n8k16.row.col.f32.f16.f16.f32 "
        "{%0,%1,%2,%3},{%4,%5,%6,%7},{%8,%9},{%0,%1,%2,%3};"
        : "+f"(c[0]), "+f"(c[1]), "+f"(c[2]), "+f"(c[3])
        : "r"(a[0]), "r"(a[1]), "r"(a[2]), "r"(a[3]), "r"(b0), "r"(b1));
}

static __device__ __forceinline__ u32 pkf16(float a, float b) {
    __half2 t = __floats2half2_rn(a, b);
    return *reinterpret_cast<u32*>(&t);
}
static __device__ __forceinline__ u32 hrelu(u32 p) {
    __half2 v = *reinterpret_cast<__half2*>(&p);
    const __half2 c = __floats2half2_rn(0.01f, 0.01f);
    __half2 r = __hmax2(v, __hmul2(v, c));
    return *reinterpret_cast<u32*>(&r);
}
static __device__ __forceinline__ void zeroC(float* C) {
#pragma unroll
    for (int i = 0; i < 32; i++) C[i] = 0.f;
}

#define ABIX(kt, t, lane) ((((kt) * 2 + (t)) * 32 + (lane)) << 4)

// ---- GEMM unit (64x64, fp16), 2 M-tiles, A from smem ----
static __device__ __forceinline__ void gemm_s2(float C0[32], float C1[32],
                                               const char* ab, const char* wt, int lane) {
#pragma unroll 2
    for (int kt = 0; kt < 4; kt++) {
        const uint4 A0 = *(const uint4*)(ab + ABIX(kt, 0, lane));
        const uint4 A1 = *(const uint4*)(ab + ABIX(kt, 1, lane));
#pragma unroll
        for (int np = 0; np < 4; np++) {
            const uint4 B = *(const uint4*)(wt + (((kt * 4 + np) * 32 + lane) << 4));
            mma_f16(C0 + (2 * np) * 4,     (const u32*)&A0, B.x, B.y);
            mma_f16(C0 + (2 * np + 1) * 4, (const u32*)&A0, B.z, B.w);
            mma_f16(C1 + (2 * np) * 4,     (const u32*)&A1, B.x, B.y);
            mma_f16(C1 + (2 * np + 1) * 4, (const u32*)&A1, B.z, B.w);
        }
    }
}
// ---- GEMM unit, A from registers (X = 32 regs: tile0 16, tile1 16) ----
static __device__ __forceinline__ void gemm_r2(float C0[32], float C1[32],
                                               const u32* X, const char* wt, int lane) {
#pragma unroll 2
    for (int kt = 0; kt < 4; kt++) {
#pragma unroll
        for (int np = 0; np < 4; np++) {
            const uint4 B = *(const uint4*)(wt + (((kt * 4 + np) * 32 + lane) << 4));
            mma_f16(C0 + (2 * np) * 4,     X + 4 * kt, B.x, B.y);
            mma_f16(C0 + (2 * np + 1) * 4, X + 4 * kt, B.z, B.w);
            mma_f16(C1 + (2 * np) * 4,     X + 16 + 4 * kt, B.x, B.y);
            mma_f16(C1 + (2 * np + 1) * 4, X + 16 + 4 * kt, B.z, B.w);
        }
    }
}

// ---- C (x 1/256, +scaled bias) -> 16 A-frag regs; relu applied packed ----
static __device__ __forceinline__ void epi1(const float C[32], const float* bias,
                                            bool relu, u32* H, int lane) {
    const int cb = (lane & 3) * 2;
#pragma unroll
    for (int nt = 0; nt < 8; nt++) {
        const float2 bb = *(const float2*)(bias + 8 * nt + cb);
        const float v0 = fmaf(C[nt * 4 + 0], INVS, bb.x), v1 = fmaf(C[nt * 4 + 1], INVS, bb.y);
        const float v2 = fmaf(C[nt * 4 + 2], INVS, bb.x), v3 = fmaf(C[nt * 4 + 3], INVS, bb.y);
        const int o = (nt >> 1) * 4 + (nt & 1) * 2;
        u32 p0 = pkf16(v0, v1), p1 = pkf16(v2, v3);
        if (relu) { p0 = hrelu(p0); p1 = hrelu(p1); }
        H[o]     = p0;
        H[o + 1] = p1;
    }
}
// ---- 32 A-frag regs -> smem buffer (lane-private) ----
static __device__ __forceinline__ void st_buf2(char* dst, const u32* X, int lane) {
#pragma unroll
    for (int kt = 0; kt < 4; kt++) {
        *(uint4*)(dst + ABIX(kt, 0, lane)) =
            make_uint4(X[4 * kt], X[4 * kt + 1], X[4 * kt + 2], X[4 * kt + 3]);
        *(uint4*)(dst + ABIX(kt, 1, lane)) =
            make_uint4(X[16 + 4 * kt], X[17 + 4 * kt], X[18 + 4 * kt], X[19 + 4 * kt]);
    }
}
// ---- gather 4 embedding rows (x256, fp16) -> 32 A-frag regs ----
static __device__ __forceinline__ void gather_r2(u32* X, const float* e0, const float* e1,
                                                 const float* e2, const float* e3, int q) {
#pragma unroll
    for (int kt = 0; kt < 4; kt++) {
        float2 a = ((const float2*)e0)[8 * kt + q];
        float2 b = ((const float2*)e1)[8 * kt + q];
        float2 c = ((const float2*)e0)[8 * kt + q + 4];
        float2 d = ((const float2*)e1)[8 * kt + q + 4];
        X[4 * kt + 0] = pkf16(a.x * SSCALE, a.y * SSCALE);
        X[4 * kt + 1] = pkf16(b.x * SSCALE, b.y * SSCALE);
        X[4 * kt + 2] = pkf16(c.x * SSCALE, c.y * SSCALE);
        X[4 * kt + 3] = pkf16(d.x * SSCALE, d.y * SSCALE);
        float2 e = ((const float2*)e2)[8 * kt + q];
        float2 f = ((const float2*)e3)[8 * kt + q];
        float2 g = ((const float2*)e2)[8 * kt + q + 4];
        float2 h = ((const float2*)e3)[8 * kt + q + 4];
        X[16 + 4 * kt + 0] = pkf16(e.x * SSCALE, e.y * SSCALE);
        X[16 + 4 * kt + 1] = pkf16(f.x * SSCALE, f.y * SSCALE);
        X[16 + 4 * kt + 2] = pkf16(g.x * SSCALE, g.y * SSCALE);
        X[16 + 4 * kt + 3] = pkf16(h.x * SSCALE, h.y * SSCALE);
    }
}

#define WT(i) (smc + OFF_W + (i) * W_TILE)

// NOT, regs -> regs (out may alias in)
static __device__ __forceinline__ void not_rr(const u32* Xin, u32* Hout,
                                              const float* bs, int lane) {
    float C0[32], C1[32]; u32 T[32];
    zeroC(C0); zeroC(C1);
    gemm_r2(C0, C1, Xin, WT(0), lane);
    epi1(C0, bs, true, T, lane); epi1(C1, bs, true, T + 16, lane);
    zeroC(C0); zeroC(C1);
    gemm_r2(C0, C1, T, WT(1), lane);
    epi1(C0, bs + 64, false, Hout, lane); epi1(C1, bs + 64, false, Hout + 16, lane);
}
// AND/OR: x1 regs @W1a, x2 smem @W1b -> Hout regs (may alias x1)
static __device__ __forceinline__ void mlp2_rs(const u32* X1, const char* b2f, u32* Hout,
                                               const char* ta, const float* bs, int lane) {
    float C0[32], C1[32]; u32 T[32];
    zeroC(C0); zeroC(C1);
    gemm_r2(C0, C1, X1, ta, lane);
    gemm_s2(C0, C1, b2f, ta + W_TILE, lane);
    epi1(C0, bs, true, T, lane); epi1(C1, bs, true, T + 16, lane);
    zeroC(C0); zeroC(C1);
    gemm_r2(C0, C1, T, ta + 2 * W_TILE, lane);
    epi1(C0, bs + 64, false, Hout, lane); epi1(C1, bs + 64, false, Hout + 16, lane);
}
// AND/OR: x1 smem @W1a, x2 regs @W1b -> Hout regs (may alias x2)
static __device__ __forceinline__ void mlp2_sr(const char* b1f, const u32* X2, u32* Hout,
                                               const char* ta, const float* bs, int lane) {
    float C0[32], C1[32]; u32 T[32];
    zeroC(C0); zeroC(C1);
    gemm_s2(C0, C1, b1f, ta, lane);
    gemm_r2(C0, C1, X2, ta + W_TILE, lane);
    epi1(C0, bs, true, T, lane); epi1(C1, bs, true, T + 16, lane);
    zeroC(C0); zeroC(C1);
    gemm_r2(C0, C1, T, ta + 2 * W_TILE, lane);
    epi1(C0, bs + 64, false, Hout, lane); epi1(C1, bs + 64, false, Hout + 16, lane);
}
// AND/OR: both operands smem -> Hout regs
static __device__ __forceinline__ void mlp2_ss(const char* b1f, const char* b2f, u32* Hout,
                                               const char* ta, const float* bs, int lane) {
    float C0[32], C1[32]; u32 T[32];
    zeroC(C0); zeroC(C1);
    gemm_s2(C0, C1, b1f, ta, lane);
    gemm_s2(C0, C1, b2f, ta + W_TILE, lane);
    epi1(C0, bs, true, T, lane); epi1(C1, bs, true, T + 16, lane);
    zeroC(C0); zeroC(C1);
    gemm_r2(C0, C1, T, ta + 2 * W_TILE, lane);
    epi1(C0, bs + 64, false, Hout, lane); epi1(C1, bs + 64, false, Hout + 16, lane);
}
// x1 smem (PRESERVED) @W1a, x2 regs @W1b; cosine epilogue -> out (4 rows)
static __device__ __forceinline__ void mlp2_cos(const char* x1, const u32* X,
                                                const char* ta, const float* bs,
                                                const float* tvs, float tvd,
                                                float* outp, int g0, int lane) {
    float C0[32], C1[32]; u32 T[32];
    zeroC(C0); zeroC(C1);
    gemm_s2(C0, C1, x1, ta, lane);
    gemm_r2(C0, C1, X, ta + W_TILE, lane);
    epi1(C0, bs, true, T, lane); epi1(C1, bs, true, T + 16, lane);
    zeroC(C0); zeroC(C1);
    gemm_r2(C0, C1, T, ta + 2 * W_TILE, lane);

    const float* b2 = bs + 64;
    const int cb = (lane & 3) * 2;
    float nu[4] = {0.f, 0.f, 0.f, 0.f}, nr[4] = {0.f, 0.f, 0.f, 0.f};
#pragma unroll
    for (int nt = 0; nt < 8; nt++) {
        const float2 bb = *(const float2*)(b2 + 8 * nt + cb);
        const float2 tv = *(const float2*)(tvs + 8 * nt + cb);
        const float* Cp[2] = { C0 + nt * 4, C1 + nt * 4 };
#pragma unroll
        for (int t = 0; t < 2; t++) {
            float v0 = fmaf(Cp[t][0], INVS, bb.x), v1 = fmaf(Cp[t][1], INVS, bb.y);
            float v2 = fmaf(Cp[t][2], INVS, bb.x), v3 = fmaf(Cp[t][3], INVS, bb.y);
            nu[2 * t + 0] = fmaf(v0, tv.x, fmaf(v1, tv.y, nu[2 * t + 0]));
            nr[2 * t + 0] = fmaf(v0, v0, fmaf(v1, v1, nr[2 * t + 0]));
            nu[2 * t + 1] = fmaf(v2, tv.x, fmaf(v3, tv.y, nu[2 * t + 1]));
            nr[2 * t + 1] = fmaf(v2, v2, fmaf(v3, v3, nr[2 * t + 1]));
        }
    }
#pragma unroll
    for (int off = 1; off <= 2; off <<= 1)
#pragma unroll
        for (int j = 0; j < 4; j++) {
            nu[j] += __shfl_xor_sync(~0u, nu[j], off);
            nr[j] += __shfl_xor_sync(~0u, nr[j], off);
        }
    if ((lane & 3) == 0) {
        outp[g0]      = nu[0] / (fmaxf(sqrtf(nr[0]), 1e-8f) * tvd) * 10.0f;
        outp[g0 + 8]  = nu[1] / (fmaxf(sqrtf(nr[1]), 1e-8f) * tvd) * 10.0f;
        outp[g0 + 16] = nu[2] / (fmaxf(sqrtf(nr[2]), 1e-8f) * tvd) * 10.0f;
        outp[g0 + 24] = nu[3] / (fmaxf(sqrtf(nr[3]), 1e-8f) * tvd) * 10.0f;
    }
}

__global__ void __launch_bounds__(TPB, 1)
logicnet_kernel(const int* __restrict__ seq,
                const int* __restrict__ pos_t,
                const int* __restrict__ neg_t,
                const float* __restrict__ item_embed,
                const float* __restrict__ g_tv,
                const float* __restrict__ nW1, const float* __restrict__ nb1,
                const float* __restrict__ nW2, const float* __restrict__ nb2,
                const float* __restrict__ aW1, const float* __restrict__ ab1,
                const float* __restrict__ aW2, const float* __restrict__ ab2,
                const float* __restrict__ oW1, const float* __restrict__ ob1,
                const float* __restrict__ oW2, const float* __restrict__ ob2,
                float* __restrict__ out) {
    const int tid = threadIdx.x, w = tid >> 5, lane = tid & 31;

    // ---- stage weights (x256, fp16) nt-paired: uint4 = {na.b0,na.b1,nb.b0,nb.b1} ----
    {
        const float* wsrc[8] = { nW1, nW2, aW1, aW1 + 4096, aW2, oW1, oW1 + 4096, oW2 };
#pragma unroll 1
        for (int e = tid; e < 4096; e += TPB) {
            const int t = e >> 9, rem = e & 511, ktnp = rem >> 5, ln = rem & 31;
            const int k0 = (ktnp >> 2) * 16 + (ln & 3) * 2;
            const int na = (ktnp & 3) * 16 + (ln >> 2);
            const int nb = na + 8;
            const float* s = wsrc[t];
            const u32 a0 = pkf16(s[(k0)     * 64 + na] * SSCALE, s[(k0 + 1) * 64 + na] * SSCALE);
            const u32 a1 = pkf16(s[(k0 + 8) * 64 + na] * SSCALE, s[(k0 + 9) * 64 + na] * SSCALE);
            const u32 b0 = pkf16(s[(k0)     * 64 + nb] * SSCALE, s[(k0 + 1) * 64 + nb] * SSCALE);
            const u32 b1 = pkf16(s[(k0 + 8) * 64 + nb] * SSCALE, s[(k0 + 9) * 64 + nb] * SSCALE);
            *(uint4*)(smc + OFF_W + (size_t)t * W_TILE + ((size_t)(ktnp * 32 + ln)) * 16) =
                make_uint4(a0, a1, b0, b1);
        }
        float* sb = (float*)(smc + OFF_BIAS);
        if (tid < 64) {
            sb[tid]       = nb1[tid] * SSCALE; sb[64 + tid]  = nb2[tid] * SSCALE;
            sb[128 + tid] = ab1[tid] * SSCALE; sb[192 + tid] = ab2[tid] * SSCALE;
            sb[256 + tid] = ob1[tid] * SSCALE; sb[320 + tid] = ob2[tid] * SSCALE;
            ((float*)(smc + OFF_TV))[tid] = g_tv[tid];
        }
    }
    __syncthreads();

    const float* BS  = (const float*)(smc + OFF_BIAS);
    const float* tvs = (const float*)(smc + OFF_TV);
    float t2 = 0.f;
#pragma unroll
    for (int c = 0; c < 64; c++) t2 = fmaf(tvs[c], tvs[c], t2);
    const float tvd = fmaxf(sqrtf(t2), 1e-8f);

    const int q = lane & 3;
    char* B0 = smc + OFF_A + w * 8192;
    char* B1 = B0 + 4096;

#define EMB(id) (item_embed + (size_t)(id) * 64)
#define GSEQ(dst, p) gather_r2(dst, EMB(seq[gA * 5 + (p)]), EMB(seq[gB * 5 + (p)]), \
                                    EMB(seq[gC * 5 + (p)]), EMB(seq[gD * 5 + (p)]), q)

    // ---- persistent work-stealing loop: each warp grabs 32-row chunks ----
#pragma unroll 1
    for (;;) {
        u32 c;
        if (lane == 0) c = atomicAdd(&g_ctr, 1u);
        c = __shfl_sync(~0u, c, 0);
        if (c >= NCHUNK) break;

        const int g0 = (int)c * 32 + (lane >> 2);
        const int gA = g0, gB = g0 + 8, gC = g0 + 16, gD = g0 + 24;

        u32 X[32], H[32];

        GSEQ(X, 1);                                   // e(seq1)
        not_rr(X, H, BS + 0, lane);                   // H = n1
        st_buf2(B0, H, lane);                         // n1 -> B0
        GSEQ(X, 0);                                   // e(seq0)
        mlp2_rs(X, B0, H, WT(2), BS + 128, lane);     // H = int5 = AND(e0@W1a, n1@W1b)
        st_buf2(B0, H, lane);                         // int5 -> B0
        GSEQ(X, 2);                                   // e(seq2)
        st_buf2(B1, X, lane);                         // e2 -> B1
        GSEQ(X, 3);                                   // e(seq3)
        mlp2_sr(B1, X, H, WT(5), BS + 256, lane);     // H = int6 = OR(e2@W1a, e3@W1b)
        st_buf2(B1, H, lane);                         // int6 -> B1
        mlp2_ss(B0, B1, H, WT(2), BS + 128, lane);    // H = int7 = AND(int5, int6)
        not_rr(H, H, BS + 0, lane);                   // H = n7
        st_buf2(B0, H, lane);                         // n7 -> B0
        GSEQ(X, 4);                                   // e(seq4)
        mlp2_sr(B0, X, H, WT(5), BS + 256, lane);     // H = out = OR(n7@W1a, e4@W1b)
        not_rr(H, H, BS + 0, lane);                   // H = enc_not
        st_buf2(B0, H, lane);                         // enc_not -> B0 (used twice)
        gather_r2(X, EMB(pos_t[gA]), EMB(pos_t[gB]), EMB(pos_t[gC]), EMB(pos_t[gD]), q);
        mlp2_cos(B0, X, WT(5), BS + 256, tvs, tvd, out, g0, lane);
        gather_r2(X, EMB(neg_t[gA]), EMB(neg_t[gB]), EMB(neg_t[gC]), EMB(neg_t[gD]), q);
        mlp2_cos(B0, X, WT(5), BS + 256, tvs, tvd, out + BATCHN, g0, lane);
    }
}

extern "C" void kernel_launch(void* const* d_in, const int* in_sizes, int n_in,
                              void* d_out, int out_size) {
    (void)in_sizes; (void)n_in; (void)out_size;
    cudaFuncSetAttribute(logicnet_kernel,
                         cudaFuncAttributeMaxDynamicSharedMemorySize, SMEM_BYTES);
    reset_ctr<<<1, 1>>>();
    logicnet_kernel<<<NBLOCKS, TPB, SMEM_BYTES>>>(
        (const int*)d_in[0], (const int*)d_in[1], (const int*)d_in[2],
        (const float*)d_in[3], (const float*)d_in[4],
        (const float*)d_in[5], (const float*)d_in[6],
        (const float*)d_in[7], (const float*)d_in[8],
        (const float*)d_in[9], (const float*)d_in[10],
        (const float*)d_in[11], (const float*)d_in[12],
        (const float*)d_in[13], (const float*)d_in[14],
        (const float*)d_in[15], (const float*)d_in[16],
        (float*)d_out);
}